// round 11
// baseline (speedup 1.0000x reference)
#include <cuda_runtime.h>
#include <cstdint>

#define BATCH 4096

// ---- uniform 32KB chunks (8192 floats) over concatenated logits ----
#define CHUNK_FLOATS 8192
#define CHUNK_BYTES  32768
#define C3_END 4096              // L3: 1 row/chunk
#define C2_END 5120              // L2: 4 rows/chunk
#define C1_END 5376              // L1: 16 rows/chunk
#define NCHUNK 5440              // L0: 64 rows/chunk

#define NB_CE 148                // 1 CTA/SM, 512 threads
#define NBD 8                    // dep folded into CTAs 0..7
#define NSTAGE 6                 // 6 x 32KB = 192KB smem, ~160KB in flight

__device__ float g_part[NB_CE];
__device__ float g_dep[NBD];
__device__ int   g_done;         // zero-init; self-resets each replay

__device__ __forceinline__ float vec_expsum(float4 v) {
    return __expf(v.x) + __expf(v.y) + __expf(v.z) + __expf(v.w);
}
__device__ __forceinline__ float warp_sum(float s) {
    #pragma unroll
    for (int off = 16; off; off >>= 1)
        s += __shfl_xor_sync(0xffffffffu, s, off);
    return s;
}
__device__ __forceinline__ uint32_t smem_u32(const void* p) {
    return (uint32_t)__cvta_generic_to_shared(p);
}
__device__ __forceinline__ void mbar_init(uint32_t a) {
    asm volatile("mbarrier.init.shared.b64 [%0], 1;" :: "r"(a) : "memory");
}
__device__ __forceinline__ void mbar_wait(uint32_t a, int parity) {
    asm volatile(
        "{\n\t.reg .pred P;\n\t"
        "W%=:\n\t"
        "mbarrier.try_wait.parity.acquire.cta.shared::cta.b64 P, [%0], %1, 0x989680;\n\t"
        "@P bra D%=;\n\t"
        "bra W%=;\n\t"
        "D%=:\n\t}"
        :: "r"(a), "r"(parity) : "memory");
}
__device__ __forceinline__ void bulk_load(uint32_t dst, const void* src,
                                          uint32_t bytes, uint32_t mbar) {
    asm volatile("mbarrier.arrive.expect_tx.shared.b64 _, [%0], %1;"
                 :: "r"(mbar), "r"(bytes) : "memory");
    asm volatile(
        "cp.async.bulk.shared::cluster.global.mbarrier::complete_tx::bytes "
        "[%0], [%1], %2, [%3];"
        :: "r"(dst), "l"(src), "r"(bytes), "r"(mbar) : "memory");
}

__global__ void __launch_bounds__(512)
fused_kernel(const float* __restrict__ o0, const float* __restrict__ o1,
             const float* __restrict__ o2, const float* __restrict__ o3,
             const int* __restrict__ targets,
             const int* __restrict__ p0, const int* __restrict__ p1,
             const int* __restrict__ p2, const int* __restrict__ p3,
             const int* __restrict__ v01, const int* __restrict__ v12,
             const int* __restrict__ v23,
             float* __restrict__ out) {
    extern __shared__ float stage[];              // NSTAGE * 8192 floats
    __shared__ unsigned long long mbar_s[NSTAGE];
    __shared__ float sws[2][16];                  // double-buffered warp partials
    __shared__ float swr[16];
    __shared__ bool  is_last;

    const int bid = blockIdx.x;
    const int tid = threadIdx.x;
    const int wid = tid >> 5;
    const int lid = tid & 31;

    float acc = 0.0f;

    uint32_t mb[NSTAGE], stg[NSTAGE];
    #pragma unroll
    for (int s = 0; s < NSTAGE; s++) {
        mb[s]  = smem_u32(&mbar_s[s]);
        stg[s] = smem_u32(&stage[s * CHUNK_FLOATS]);
    }
    if (tid == 0) {
        #pragma unroll
        for (int s = 0; s < NSTAGE; s++) mbar_init(mb[s]);
    }
    __syncthreads();

    auto src_of = [&](int c) -> const float* {
        if (c < C3_END) return o3 + (size_t)c * CHUNK_FLOATS;
        if (c < C2_END) return o2 + (size_t)(c - C3_END) * CHUNK_FLOATS;
        if (c < C1_END) return o1 + (size_t)(c - C2_END) * CHUNK_FLOATS;
        return o0 + (size_t)(c - C1_END) * CHUNK_FLOATS;
    };

    // Fill all 6 stages (bid + 5*148 = max 887 < NCHUNK always).
    if (tid == 0) {
        #pragma unroll
        for (int kp = 0; kp < NSTAGE; kp++)
            bulk_load(stg[kp], src_of(bid + kp * NB_CE), CHUNK_BYTES, mb[kp]);
    }

    // ---- dep work folded into CTAs 0..7, hidden under pipeline fill ----
    if (bid < NBD) {
        const int i = bid * 512 + tid;
        const int a = p0[i], b = p1[i], cc = p2[i], e = p3[i];
        float cnt = 0.0f;
        cnt += (v01[a * 512   + b ] == 0) ? 1.0f : 0.0f;
        cnt += (v12[b * 2048  + cc] == 0) ? 1.0f : 0.0f;
        cnt += (v23[cc * 8192 + e ] == 0) ? 1.0f : 0.0f;
        cnt = warp_sum(cnt);
        if (lid == 0) swr[wid] = cnt;
        __syncthreads();
        if (tid == 0) {
            float a2 = 0.0f;
            #pragma unroll
            for (int w = 0; w < 16; w++) a2 += swr[w];
            g_dep[bid] = a2;
        }
        __syncthreads();
    }

    // ---- main pipelined loop ----
    for (int k = 0, c = bid; c < NCHUNK; k++, c += NB_CE) {
        const int s = k % NSTAGE;
        const int parity = (k / NSTAGE) & 1;
        const int pb = k & 1;
        mbar_wait(mb[s], parity);

        const float*  sf = stage + s * CHUNK_FLOATS;
        const float4* st = (const float4*)sf;

        if (c < C1_END) {
            // Unified slice for L3/L2/L1: warp reads 128 float4 at wid*128.
            const float4* wp = st + wid * 128;
            // L1: leader pre-loads its target index to overlap the exp chain.
            int tIdx = 0;
            if (c >= C2_END && lid == 0)
                tIdx = targets[((c - C2_END) * 16 + wid) * 4 + 1];

            float4 v0 = wp[0 * 32 + lid];
            float4 v1 = wp[1 * 32 + lid];
            float4 v2 = wp[2 * 32 + lid];
            float4 v3 = wp[3 * 32 + lid];
            float sv = warp_sum((vec_expsum(v0) + vec_expsum(v1)) +
                                (vec_expsum(v2) + vec_expsum(v3)));

            if (c < C2_END) {
                if (lid == 0) sws[pb][wid] = sv;
            } else if (lid == 0) {
                acc += __logf(sv) - sf[wid * 512 + tIdx];   // L1 row done in-warp
            }
        } else {
            // L0: 64 rows of 128; 4 rows/warp, 8 lanes/row.
            const int rl = wid * 4 + (lid >> 3);
            const int sl = lid & 7;
            int tIdx = 0;
            if (sl == 0) tIdx = targets[((c - C1_END) * 64 + rl) * 4 + 0];
            const float4* gp = st + rl * 32;
            float a0 = vec_expsum(gp[0 * 8 + sl]) + vec_expsum(gp[1 * 8 + sl]);
            float a1 = vec_expsum(gp[2 * 8 + sl]) + vec_expsum(gp[3 * 8 + sl]);
            float sv = a0 + a1;
            #pragma unroll
            for (int off = 4; off; off >>= 1)
                sv += __shfl_xor_sync(0xffffffffu, sv, off);
            if (sl == 0) acc += __logf(sv) - sf[rl * 128 + tIdx];
        }

        __syncthreads();   // all reads of stage s complete; sws[pb] published

        if (tid == 0) {
            if (c < C3_END) {
                float t0s = 0.0f;
                #pragma unroll
                for (int w = 0; w < 16; w++) t0s += sws[pb][w];
                const int t = targets[c * 4 + 3];
                acc += __logf(t0s) - sf[t];
            } else if (c < C2_END) {
                const int rb = (c - C3_END) * 4;
                #pragma unroll
                for (int j = 0; j < 4; j++) {
                    float rs = (sws[pb][4 * j] + sws[pb][4 * j + 1]) +
                               (sws[pb][4 * j + 2] + sws[pb][4 * j + 3]);
                    const int t = targets[(rb + j) * 4 + 2];
                    acc += __logf(rs) - sf[j * 2048 + t];
                }
            }
            const int cn = c + NSTAGE * NB_CE;
            if (cn < NCHUNK) {
                asm volatile("fence.proxy.async.shared::cta;" ::: "memory");
                bulk_load(stg[s], src_of(cn), CHUNK_BYTES, mb[s]);
            }
        }
    }

    // ---- per-CTA combine ----
    float ws = warp_sum(acc);
    __syncthreads();
    if (lid == 0) swr[wid] = ws;
    __syncthreads();
    if (tid == 0) {
        float a = 0.0f;
        #pragma unroll
        for (int w = 0; w < 16; w++) a += swr[w];
        g_part[bid] = a;
    }

    // ---- last-block finalize ----
    if (tid == 0) {
        __threadfence();
        int ticket = atomicAdd(&g_done, 1);
        is_last = (ticket == NB_CE - 1);
        if (is_last) g_done = 0;
    }
    __syncthreads();

    if (is_last) {
        float ce = (tid < NB_CE) ? __ldcg(&g_part[tid]) : 0.0f;
        ce = warp_sum(ce);
        __syncthreads();
        if (lid == 0) swr[wid] = ce;
        __syncthreads();
        if (tid == 0) {
            float ce_sum = 0.0f;
            #pragma unroll
            for (int w = 0; w < 16; w++) ce_sum += swr[w];
            float depcnt = 0.0f;
            #pragma unroll
            for (int j = 0; j < NBD; j++) depcnt += __ldcg(&g_dep[j]);

            const float E_MINUS_1 = 1.7182818284590452f;
            const float inv_b = 1.0f / (float)BATCH;
            float ce_total  = ce_sum * inv_b;
            float dep_total = E_MINUS_1 * depcnt * inv_b;
            out[0] = 0.5f * ce_total + 0.5f * dep_total;
            out[1] = ce_total;
            out[2] = dep_total;
        }
    }
}

extern "C" void kernel_launch(void* const* d_in, const int* in_sizes, int n_in,
                              void* d_out, int out_size) {
    const float* o0 = (const float*)d_in[0];
    const float* o1 = (const float*)d_in[1];
    const float* o2 = (const float*)d_in[2];
    const float* o3 = (const float*)d_in[3];
    const int* targets = (const int*)d_in[4];
    const int* p0 = (const int*)d_in[5];
    const int* p1 = (const int*)d_in[6];
    const int* p2 = (const int*)d_in[7];
    const int* p3 = (const int*)d_in[8];
    const int* v01 = (const int*)d_in[9];
    const int* v12 = (const int*)d_in[10];
    const int* v23 = (const int*)d_in[11];
    float* out = (float*)d_out;

    const size_t smem = NSTAGE * CHUNK_BYTES;   // 196608 B
    cudaFuncSetAttribute(fused_kernel,
                         cudaFuncAttributeMaxDynamicSharedMemorySize, (int)smem);
    fused_kernel<<<NB_CE, 512, smem>>>(o0, o1, o2, o3, targets,
                                       p0, p1, p2, p3, v01, v12, v23, out);
}